// round 9
// baseline (speedup 1.0000x reference)
#include <cuda_runtime.h>
#include <cstdint>

typedef unsigned long long u64;

// ---------- device scratch ----------
__device__ float g_feat[4 * 64 * 64 * 64];      // NHWC feat[pix][64]
__device__ float g_wk[4 * 64 * 64 * 100];       // softmaxed kernels
__device__ u64   g_wc2[4 * 256 * 8];            // k1 weights: [quarter][c][8] pairs (m,m+1)
__device__ u64   g_wp2[64 * 9 * 4 * 14];        // k2 weights: [i][t][p][14] pairs (k,k+1), padded
__device__ float g_dummy[128];                  // dummy kernel target (profiling slot shim)

// ---------- f32x2 helpers ----------
__device__ __forceinline__ u64 pack2(float lo, float hi) {
    u64 r; asm("mov.b64 %0, {%1, %2};" : "=l"(r) : "f"(lo), "f"(hi)); return r;
}
__device__ __forceinline__ void unpack2(u64 v, float& lo, float& hi) {
    asm("mov.b64 {%0, %1}, %2;" : "=f"(lo), "=f"(hi) : "l"(v));
}
__device__ __forceinline__ u64 fma2(u64 a, u64 b, u64 c) {
    u64 d; asm("fma.rn.f32x2 %0, %1, %2, %3;" : "=l"(d) : "l"(a), "l"(b), "l"(c)); return d;
}

// ============================================================
// K0: pack weights
//   g_wc2[qr][c][j] = (Wc[qr*16+2j, c], Wc[qr*16+2j+1, c])          (8192)
//   g_wp2[i][t][p][kp] = (We[p*25+2kp, i, t], We[p*25+2kp+1, i, t]) (32256, padded)
// ============================================================
__global__ void k0_pack(const float* __restrict__ Wc, const float* __restrict__ We) {
    int e = blockIdx.x * 256 + threadIdx.x;
    if (e < 8192) {
        int j = e & 7, c = (e >> 3) & 255, qr = e >> 11;
        int m0 = qr * 16 + 2 * j;
        g_wc2[e] = pack2(Wc[(size_t)m0 * 256 + c], Wc[(size_t)(m0 + 1) * 256 + c]);
    } else if (e < 8192 + 32256) {
        int e2 = e - 8192;
        int kp = e2 % 14;
        int p  = (e2 / 14) & 3;
        int t  = (e2 / 56) % 9;
        int i  = e2 / 504;
        int o0 = p * 25 + 2 * kp;
        float lo = (2 * kp < 25)     ? We[(size_t)o0 * 576 + i * 9 + t] : 0.f;
        float hi = (2 * kp + 1 < 25) ? We[(size_t)(o0 + 1) * 576 + i * 9 + t] : 0.f;
        g_wp2[e2] = pack2(lo, hi);
    }
}

// ============================================================
// K1: feat = relu(Wc @ x + bc), NHWC output — quarter-split for occupancy
//   grid 512 (128 px-groups x 4 m-quarters) x 128 threads
//   1 px/thread, 16 outputs (8 u64 acc), 16KB smem weights, ~14 warps/SM
// ============================================================
#define K1_SMEM (2048 * 8)

__global__ __launch_bounds__(128) void k1_compress(const float* __restrict__ x,
                                                   const float* __restrict__ bc) {
    extern __shared__ u64 ws[];      // [256][8] packed pairs for this quarter
    int tid = threadIdx.x;
    int qr  = blockIdx.x & 3;
    int pix = (blockIdx.x >> 2) * 128 + tid;

    const u64* src = g_wc2 + qr * 2048;
    for (int e = tid; e < 2048; e += 128) ws[e] = src[e];
    __syncthreads();

    int bb = pix >> 12, hw = pix & 4095;
    const float* xp = x + ((size_t)bb << 20) + hw;

    u64 acc[8];
#pragma unroll
    for (int j = 0; j < 8; j++) acc[j] = 0ull;

    for (int c = 0; c < 256; c += 4) {
        float xv[4];
#pragma unroll
        for (int u = 0; u < 4; u++) xv[u] = __ldg(xp + (size_t)(c + u) * 4096);
#pragma unroll
        for (int u = 0; u < 4; u++) {
            u64 v2 = pack2(xv[u], xv[u]);
            const ulonglong2* wr = (const ulonglong2*)(ws + (size_t)(c + u) * 8);
#pragma unroll
            for (int q = 0; q < 4; q++) {
                ulonglong2 ww = wr[q];
                acc[2 * q + 0] = fma2(v2, ww.x, acc[2 * q + 0]);
                acc[2 * q + 1] = fma2(v2, ww.y, acc[2 * q + 1]);
            }
        }
    }

    float* dst = g_feat + (size_t)pix * 64 + qr * 16;
#pragma unroll
    for (int q = 0; q < 4; q++) {
        float f0, f1, f2, f3;
        unpack2(acc[2 * q + 0], f0, f1);
        unpack2(acc[2 * q + 1], f2, f3);
        int m0 = qr * 16 + 4 * q;
        float4 v;
        v.x = fmaxf(f0 + __ldg(bc + m0 + 0), 0.f);
        v.y = fmaxf(f1 + __ldg(bc + m0 + 1), 0.f);
        v.z = fmaxf(f2 + __ldg(bc + m0 + 2), 0.f);
        v.w = fmaxf(f3 + __ldg(bc + m0 + 3), 0.f);
        ((float4*)dst)[q] = v;
    }
}

// ============================================================
// KD: dummy shim — makes K2 the 4th launch so ncu profiles it
// ============================================================
__global__ void kd_shim(const float* __restrict__ benc) {
    int t = threadIdx.x;
    if (t < 100) g_dummy[t] = benc[t];
}

// ============================================================
// K2: 3x3 conv (64 -> 100) + bias + softmax over 25 taps (R2 version EXACT)
// ============================================================
#define K2_FS_BYTES (64 * 200 * 4)               // 51200
#define K2_WQ_BYTES (4032 * 8)                   // 32256
#define K2_SMEM (K2_FS_BYTES + K2_WQ_BYTES)

__global__ __launch_bounds__(128) void k2_conv_softmax(const float* __restrict__ benc) {
    extern __shared__ char sm2[];
    float* fs = (float*)sm2;                     // [64 i][200] (3 rows x 66 cols, pad)
    u64* wq = (u64*)(sm2 + K2_FS_BYTES);         // [8 ii][9 t][4 p][14]

    int tid = threadIdx.x;
    int bb = blockIdx.x >> 6;
    int y  = blockIdx.x & 63;
    int xp = tid & 31;        // pixel pair: cols 2xp, 2xp+1
    int p  = tid >> 5;        // 0..3 (one warp per p)

    for (int pos = tid; pos < 198; pos += 128) {
        int r = pos / 66, cc = pos % 66;
        int iy = y + r - 1, ix = cc - 1;
        if (((unsigned)iy < 64u) && ((unsigned)ix < 64u)) {
            const float4* s4 = (const float4*)(g_feat + ((size_t)((bb * 64 + iy) * 64 + ix) << 6));
#pragma unroll
            for (int i0 = 0; i0 < 64; i0 += 4) {
                float4 v = s4[i0 >> 2];
                fs[(i0 + 0) * 200 + pos] = v.x;
                fs[(i0 + 1) * 200 + pos] = v.y;
                fs[(i0 + 2) * 200 + pos] = v.z;
                fs[(i0 + 3) * 200 + pos] = v.w;
            }
        } else {
#pragma unroll
            for (int i0 = 0; i0 < 64; i0++) fs[i0 * 200 + pos] = 0.f;
        }
    }

    u64 acc[28];              // [px(2)][14]
#pragma unroll
    for (int j = 0; j < 28; j++) acc[j] = 0ull;

    for (int chunk = 0; chunk < 8; chunk++) {
        __syncthreads();
        for (int e = tid; e < 4032; e += 128) wq[e] = g_wp2[chunk * 4032 + e];
        __syncthreads();

#pragma unroll 1
        for (int ii = 0; ii < 8; ii++) {
            const float* fr = fs + (chunk * 8 + ii) * 200;
            float win[3][4];
#pragma unroll
            for (int dy = 0; dy < 3; dy++) {
                const float2* rp = (const float2*)(fr + dy * 66 + 2 * xp);
                float2 a = rp[0], b = rp[1];
                win[dy][0] = a.x; win[dy][1] = a.y; win[dy][2] = b.x; win[dy][3] = b.y;
            }
#pragma unroll
            for (int t = 0; t < 9; t++) {
                int dy = t / 3, dx = t % 3;
                u64 v0 = pack2(win[dy][dx], win[dy][dx]);
                u64 v1 = pack2(win[dy][dx + 1], win[dy][dx + 1]);
                const ulonglong2* wr = (const ulonglong2*)(wq + (size_t)((ii * 9 + t) * 4 + p) * 14);
#pragma unroll
                for (int q = 0; q < 7; q++) {
                    ulonglong2 ww = wr[q];
                    acc[2 * q + 0]      = fma2(v0, ww.x, acc[2 * q + 0]);
                    acc[2 * q + 1]      = fma2(v0, ww.y, acc[2 * q + 1]);
                    acc[14 + 2 * q + 0] = fma2(v1, ww.x, acc[14 + 2 * q + 0]);
                    acc[14 + 2 * q + 1] = fma2(v1, ww.y, acc[14 + 2 * q + 1]);
                }
            }
        }
    }

#pragma unroll
    for (int px = 0; px < 2; px++) {
        float l[25];
#pragma unroll
        for (int kp = 0; kp < 13; kp++) {
            float lo, hi;
            unpack2(acc[px * 14 + kp], lo, hi);
            l[2 * kp] = lo;
            if (2 * kp + 1 < 25) l[2 * kp + 1] = hi;
        }
        float mx = -1e30f;
#pragma unroll
        for (int k = 0; k < 25; k++) {
            l[k] += __ldg(benc + p * 25 + k);
            mx = fmaxf(mx, l[k]);
        }
        float s = 0.f;
#pragma unroll
        for (int k = 0; k < 25; k++) {
            float e = __expf(l[k] - mx);
            l[k] = e;
            s += e;
        }
        float inv = 1.f / s;
        float* dst = g_wk + (size_t)((bb * 64 + y) * 64 + 2 * xp + px) * 100 + p * 25;
#pragma unroll
        for (int k = 0; k < 25; k++) dst[k] = l[k] * inv;
    }
}

// ============================================================
// K3: content-aware gather (R3 version EXACT — measured 41.1/41.2us)
// ============================================================
__device__ __forceinline__ float4 fetch4(const float* __restrict__ x, int bb, int c, int h, int e) {
    int row = e / 68, col = e % 68;
    int iy = h + row - 2, ix = col - 2;
    float4 v = make_float4(0.f, 0.f, 0.f, 0.f);
    if ((unsigned)iy < 64u && (unsigned)ix < 64u) {
        const float* b = x + (((size_t)(bb * 256 + c)) << 12) + (iy << 6) + ix;
        v.x = __ldg(b);
        v.y = __ldg(b + 4096);
        v.z = __ldg(b + 8192);
        v.w = __ldg(b + 12288);
    }
    return v;
}

__global__ __launch_bounds__(256) void k3_gather(const float* __restrict__ x,
                                                 float* __restrict__ out) {
    __shared__ float wk_s[6400];
    __shared__ float4 xs[2][340];

    int tid = threadIdx.x;
    int cg = blockIdx.x & 3;
    int h  = (blockIdx.x >> 2) & 63;
    int bb = blockIdx.x >> 8;
    int w = tid >> 2;
    int p = tid & 3;
    int cbase = cg * 64;

    {
        const float4* src = (const float4*)(g_wk + (size_t)(bb * 4096 + h * 64) * 100);
        float4* dst = (float4*)wk_s;
        for (int i = tid; i < 1600; i += 256) dst[i] = src[i];
    }

    int e1 = tid;
    int e2 = tid + 256;
    bool has2 = (e2 < 340);

    float4 pf1 = fetch4(x, bb, cbase, h, e1);
    float4 pf2 = has2 ? fetch4(x, bb, cbase, h, e2) : make_float4(0, 0, 0, 0);
    xs[0][e1] = pf1;
    if (has2) xs[0][e2] = pf2;
    __syncthreads();

    u64 wk2[25];
#pragma unroll
    for (int k = 0; k < 25; k++) {
        float v = wk_s[w * 100 + p * 25 + k];
        wk2[k] = pack2(v, v);
    }

    size_t obase = ((size_t)(bb * 256 + cbase) * 4096 + (h << 6) + w) * 4 + p;

    for (int it = 0; it < 16; it++) {
        int cur = it & 1;
        if (it < 15) {
            pf1 = fetch4(x, bb, cbase + (it + 1) * 4, h, e1);
            if (has2) pf2 = fetch4(x, bb, cbase + (it + 1) * 4, h, e2);
        }

        u64 a01 = 0ull, a23 = 0ull;
        const ulonglong2* q = (const ulonglong2*)xs[cur];
#pragma unroll
        for (int k = 0; k < 25; k++) {
            int off = (k / 5) * 68 + w + (k % 5);
            ulonglong2 v = q[off];
            a01 = fma2(v.x, wk2[k], a01);
            a23 = fma2(v.y, wk2[k], a23);
        }

        if (it < 15) {
            xs[cur ^ 1][e1] = pf1;
            if (has2) xs[cur ^ 1][e2] = pf2;
        }

        float o0, o1, o2, o3;
        unpack2(a01, o0, o1);
        unpack2(a23, o2, o3);
        size_t ob = obase + (size_t)it * 4 * 16384;
        out[ob + 0 * 16384] = o0;
        out[ob + 1 * 16384] = o1;
        out[ob + 2 * 16384] = o2;
        out[ob + 3 * 16384] = o3;

        __syncthreads();
    }
}

// ============================================================
// launch: k0, k1, shim, k2 (4th -> profiled), k3
// ============================================================
extern "C" void kernel_launch(void* const* d_in, const int* in_sizes, int n_in,
                              void* d_out, int out_size) {
    (void)in_sizes; (void)n_in; (void)out_size;
    const float* x     = (const float*)d_in[0];
    const float* Wcomp = (const float*)d_in[1];
    const float* bcomp = (const float*)d_in[2];
    const float* Wenc  = (const float*)d_in[3];
    const float* benc  = (const float*)d_in[4];
    float* out = (float*)d_out;

    cudaFuncSetAttribute(k1_compress, cudaFuncAttributeMaxDynamicSharedMemorySize, K1_SMEM);
    cudaFuncSetAttribute(k2_conv_softmax, cudaFuncAttributeMaxDynamicSharedMemorySize, K2_SMEM);

    k0_pack<<<(8192 + 32256 + 255) / 256, 256>>>(Wcomp, Wenc);
    k1_compress<<<512, 128, K1_SMEM>>>(x, bcomp);
    kd_shim<<<1, 128>>>(benc);
    k2_conv_softmax<<<256, 128, K2_SMEM>>>(benc);
    k3_gather<<<1024, 256>>>(x, out);
}

// round 10
// speedup vs baseline: 1.0940x; 1.0940x over previous
#include <cuda_runtime.h>
#include <cstdint>

typedef unsigned long long u64;

// ---------- device scratch ----------
__device__ float g_feat[4 * 64 * 64 * 64];      // NHWC feat[pix][64]
__device__ float g_wk[4 * 64 * 64 * 100];       // softmaxed kernels
__device__ u64   g_wc2[2 * 256 * 16];           // k1 weights: [hf][c][16] pairs (m,m+1)
__device__ u64   g_wp2[64 * 9 * 4 * 14];        // k2 weights: [i][t][p][14] pairs (k,k+1), padded
__device__ float g_dummy[128];                  // profiling slot shim target

// ---------- f32x2 helpers ----------
__device__ __forceinline__ u64 pack2(float lo, float hi) {
    u64 r; asm("mov.b64 %0, {%1, %2};" : "=l"(r) : "f"(lo), "f"(hi)); return r;
}
__device__ __forceinline__ void unpack2(u64 v, float& lo, float& hi) {
    asm("mov.b64 {%0, %1}, %2;" : "=f"(lo), "=f"(hi) : "l"(v));
}
__device__ __forceinline__ u64 fma2(u64 a, u64 b, u64 c) {
    u64 d; asm("fma.rn.f32x2 %0, %1, %2, %3;" : "=l"(d) : "l"(a), "l"(b), "l"(c)); return d;
}

// ============================================================
// K0: pack weights (R2 version)
// ============================================================
__global__ void k0_pack(const float* __restrict__ Wc, const float* __restrict__ We) {
    int e = blockIdx.x * 256 + threadIdx.x;
    if (e < 8192) {
        int j = e & 15, c = (e >> 4) & 255, hf = e >> 12;
        int m0 = hf * 32 + 2 * j;
        g_wc2[e] = pack2(Wc[(size_t)m0 * 256 + c], Wc[(size_t)(m0 + 1) * 256 + c]);
    } else if (e < 8192 + 32256) {
        int e2 = e - 8192;
        int kp = e2 % 14;
        int p  = (e2 / 14) & 3;
        int t  = (e2 / 56) % 9;
        int i  = e2 / 504;
        int o0 = p * 25 + 2 * kp;
        float lo = (2 * kp < 25)     ? We[(size_t)o0 * 576 + i * 9 + t] : 0.f;
        float hi = (2 * kp + 1 < 25) ? We[(size_t)(o0 + 1) * 576 + i * 9 + t] : 0.f;
        g_wp2[e2] = pack2(lo, hi);
    }
}

// ============================================================
// K1: feat = relu(Wc @ x + bc), NHWC output (R2 half-split — measured best)
// ============================================================
#define K1_SMEM (4096 * 8)

__global__ __launch_bounds__(128) void k1_compress(const float* __restrict__ x,
                                                   const float* __restrict__ bc) {
    extern __shared__ u64 ws[];
    int tid = threadIdx.x;
    int hf  = blockIdx.x & 1;
    int pix = (blockIdx.x >> 1) * 128 + tid;

    const u64* src = g_wc2 + hf * 4096;
    for (int e = tid; e < 4096; e += 128) ws[e] = src[e];
    __syncthreads();

    int bb = pix >> 12, hw = pix & 4095;
    const float* xp = x + ((size_t)bb << 20) + hw;

    u64 acc[16];
#pragma unroll
    for (int j = 0; j < 16; j++) acc[j] = 0ull;

    for (int c = 0; c < 256; c += 4) {
        float xv[4];
#pragma unroll
        for (int u = 0; u < 4; u++) xv[u] = __ldg(xp + (size_t)(c + u) * 4096);
#pragma unroll
        for (int u = 0; u < 4; u++) {
            u64 v2 = pack2(xv[u], xv[u]);
            const ulonglong2* wr = (const ulonglong2*)(ws + (size_t)(c + u) * 16);
#pragma unroll
            for (int q = 0; q < 8; q++) {
                ulonglong2 ww = wr[q];
                acc[2 * q + 0] = fma2(v2, ww.x, acc[2 * q + 0]);
                acc[2 * q + 1] = fma2(v2, ww.y, acc[2 * q + 1]);
            }
        }
    }

    float* dst = g_feat + (size_t)pix * 64 + hf * 32;
#pragma unroll
    for (int q = 0; q < 8; q++) {
        float f0, f1, f2, f3;
        unpack2(acc[2 * q + 0], f0, f1);
        unpack2(acc[2 * q + 1], f2, f3);
        int m0 = hf * 32 + 4 * q;
        float4 v;
        v.x = fmaxf(f0 + __ldg(bc + m0 + 0), 0.f);
        v.y = fmaxf(f1 + __ldg(bc + m0 + 1), 0.f);
        v.z = fmaxf(f2 + __ldg(bc + m0 + 2), 0.f);
        v.w = fmaxf(f3 + __ldg(bc + m0 + 3), 0.f);
        ((float4*)dst)[q] = v;
    }
}

// ============================================================
// KD: dummy shim — keeps K2 in the 4th (profiled) launch slot
// ============================================================
__global__ void kd_shim(const float* __restrict__ benc) {
    int t = threadIdx.x;
    if (t < 100) g_dummy[t] = benc[t];
}

// ============================================================
// K2: 3x3 conv (64 -> 100) + bias + softmax — OCCUPANCY-DOUBLED version
//   grid 512 (b, y, x-half) x 128 threads; thread = (pixel, p); warp = fixed p
//   2048 warps total (13.8/SM, was 6.9); smem 59KB -> ~3.5 blocks/SM
//   feat tile: 3 rows x 34 cols for this half-row; weights: 8i-chunks (broadcast LDS)
// ============================================================
#define K2_FS_FLOATS (64 * 104)                   // [64 i][3*34 pad 104]
#define K2_FS_BYTES (K2_FS_FLOATS * 4)            // 26624
#define K2_WQ_BYTES (4032 * 8)                    // 32256
#define K2_SMEM (K2_FS_BYTES + K2_WQ_BYTES)       // 58880

__global__ __launch_bounds__(128) void k2_conv_softmax(const float* __restrict__ benc) {
    extern __shared__ char sm2[];
    float* fs = (float*)sm2;                      // [64 i][104] (3 rows x 34 cols)
    u64* wq = (u64*)(sm2 + K2_FS_BYTES);          // [8 ii][9 t][4 p][14]

    int tid = threadIdx.x;
    int xh = blockIdx.x & 1;
    int y  = (blockIdx.x >> 1) & 63;
    int bb = blockIdx.x >> 7;
    int p  = tid >> 5;        // warp id = p  -> weight LDS is warp-broadcast
    int px = tid & 31;        // pixel within half-row
    int x  = xh * 32 + px;

    // stage feat rows y-1..y+1, cols xh*32-1 .. xh*32+32 (102 positions)
    if (tid < 102) {
        int r = tid / 34, cc = tid % 34;
        int iy = y + r - 1, ix = xh * 32 + cc - 1;
        if (((unsigned)iy < 64u) && ((unsigned)ix < 64u)) {
            const float4* s4 = (const float4*)(g_feat + ((size_t)((bb * 64 + iy) * 64 + ix) << 6));
#pragma unroll
            for (int i0 = 0; i0 < 64; i0 += 4) {
                float4 v = s4[i0 >> 2];
                fs[(i0 + 0) * 104 + tid] = v.x;
                fs[(i0 + 1) * 104 + tid] = v.y;
                fs[(i0 + 2) * 104 + tid] = v.z;
                fs[(i0 + 3) * 104 + tid] = v.w;
            }
        } else {
#pragma unroll
            for (int i0 = 0; i0 < 64; i0++) fs[i0 * 104 + tid] = 0.f;
        }
    }

    u64 acc[13];
#pragma unroll
    for (int j = 0; j < 13; j++) acc[j] = 0ull;

    for (int chunk = 0; chunk < 8; chunk++) {
        __syncthreads();
        for (int e = tid; e < 4032; e += 128) wq[e] = g_wp2[chunk * 4032 + e];
        __syncthreads();

#pragma unroll 1
        for (int ii = 0; ii < 8; ii++) {
            const float* fr = fs + (chunk * 8 + ii) * 104 + px;
            float win[9];
#pragma unroll
            for (int dy = 0; dy < 3; dy++)
#pragma unroll
                for (int dx = 0; dx < 3; dx++) win[dy * 3 + dx] = fr[dy * 34 + dx];
#pragma unroll
            for (int t = 0; t < 9; t++) {
                u64 v2 = pack2(win[t], win[t]);
                const ulonglong2* wr = (const ulonglong2*)(wq + (size_t)((ii * 9 + t) * 4 + p) * 14);
#pragma unroll
                for (int q = 0; q < 6; q++) {
                    ulonglong2 ww = wr[q];
                    acc[2 * q + 0] = fma2(v2, ww.x, acc[2 * q + 0]);
                    acc[2 * q + 1] = fma2(v2, ww.y, acc[2 * q + 1]);
                }
                acc[12] = fma2(v2, wr[6].x, acc[12]);
            }
        }
    }

    // bias + softmax over the 25 taps + store
    float l[25];
#pragma unroll
    for (int kp = 0; kp < 13; kp++) {
        float lo, hi;
        unpack2(acc[kp], lo, hi);
        l[2 * kp] = lo;
        if (2 * kp + 1 < 25) l[2 * kp + 1] = hi;
    }
    float mx = -1e30f;
#pragma unroll
    for (int k = 0; k < 25; k++) {
        l[k] += __ldg(benc + p * 25 + k);
        mx = fmaxf(mx, l[k]);
    }
    float s = 0.f;
#pragma unroll
    for (int k = 0; k < 25; k++) {
        float e = __expf(l[k] - mx);
        l[k] = e;
        s += e;
    }
    float inv = 1.f / s;
    float* dst = g_wk + (size_t)((bb * 64 + y) * 64 + x) * 100 + p * 25;
#pragma unroll
    for (int k = 0; k < 25; k++) dst[k] = l[k] * inv;
}

// ============================================================
// K3: content-aware gather (R3 version EXACT — measured 41.1/41.2us)
// ============================================================
__device__ __forceinline__ float4 fetch4(const float* __restrict__ x, int bb, int c, int h, int e) {
    int row = e / 68, col = e % 68;
    int iy = h + row - 2, ix = col - 2;
    float4 v = make_float4(0.f, 0.f, 0.f, 0.f);
    if ((unsigned)iy < 64u && (unsigned)ix < 64u) {
        const float* b = x + (((size_t)(bb * 256 + c)) << 12) + (iy << 6) + ix;
        v.x = __ldg(b);
        v.y = __ldg(b + 4096);
        v.z = __ldg(b + 8192);
        v.w = __ldg(b + 12288);
    }
    return v;
}

__global__ __launch_bounds__(256) void k3_gather(const float* __restrict__ x,
                                                 float* __restrict__ out) {
    __shared__ float wk_s[6400];
    __shared__ float4 xs[2][340];

    int tid = threadIdx.x;
    int cg = blockIdx.x & 3;
    int h  = (blockIdx.x >> 2) & 63;
    int bb = blockIdx.x >> 8;
    int w = tid >> 2;
    int p = tid & 3;
    int cbase = cg * 64;

    {
        const float4* src = (const float4*)(g_wk + (size_t)(bb * 4096 + h * 64) * 100);
        float4* dst = (float4*)wk_s;
        for (int i = tid; i < 1600; i += 256) dst[i] = src[i];
    }

    int e1 = tid;
    int e2 = tid + 256;
    bool has2 = (e2 < 340);

    float4 pf1 = fetch4(x, bb, cbase, h, e1);
    float4 pf2 = has2 ? fetch4(x, bb, cbase, h, e2) : make_float4(0, 0, 0, 0);
    xs[0][e1] = pf1;
    if (has2) xs[0][e2] = pf2;
    __syncthreads();

    u64 wk2[25];
#pragma unroll
    for (int k = 0; k < 25; k++) {
        float v = wk_s[w * 100 + p * 25 + k];
        wk2[k] = pack2(v, v);
    }

    size_t obase = ((size_t)(bb * 256 + cbase) * 4096 + (h << 6) + w) * 4 + p;

    for (int it = 0; it < 16; it++) {
        int cur = it & 1;
        if (it < 15) {
            pf1 = fetch4(x, bb, cbase + (it + 1) * 4, h, e1);
            if (has2) pf2 = fetch4(x, bb, cbase + (it + 1) * 4, h, e2);
        }

        u64 a01 = 0ull, a23 = 0ull;
        const ulonglong2* q = (const ulonglong2*)xs[cur];
#pragma unroll
        for (int k = 0; k < 25; k++) {
            int off = (k / 5) * 68 + w + (k % 5);
            ulonglong2 v = q[off];
            a01 = fma2(v.x, wk2[k], a01);
            a23 = fma2(v.y, wk2[k], a23);
        }

        if (it < 15) {
            xs[cur ^ 1][e1] = pf1;
            if (has2) xs[cur ^ 1][e2] = pf2;
        }

        float o0, o1, o2, o3;
        unpack2(a01, o0, o1);
        unpack2(a23, o2, o3);
        size_t ob = obase + (size_t)it * 4 * 16384;
        out[ob + 0 * 16384] = o0;
        out[ob + 1 * 16384] = o1;
        out[ob + 2 * 16384] = o2;
        out[ob + 3 * 16384] = o3;

        __syncthreads();
    }
}

// ============================================================
// launch: k0, k1, shim, k2 (4th -> profiled), k3
// ============================================================
extern "C" void kernel_launch(void* const* d_in, const int* in_sizes, int n_in,
                              void* d_out, int out_size) {
    (void)in_sizes; (void)n_in; (void)out_size;
    const float* x     = (const float*)d_in[0];
    const float* Wcomp = (const float*)d_in[1];
    const float* bcomp = (const float*)d_in[2];
    const float* Wenc  = (const float*)d_in[3];
    const float* benc  = (const float*)d_in[4];
    float* out = (float*)d_out;

    cudaFuncSetAttribute(k1_compress, cudaFuncAttributeMaxDynamicSharedMemorySize, K1_SMEM);
    cudaFuncSetAttribute(k2_conv_softmax, cudaFuncAttributeMaxDynamicSharedMemorySize, K2_SMEM);

    k0_pack<<<(8192 + 32256 + 255) / 256, 256>>>(Wcomp, Wenc);
    k1_compress<<<256, 128, K1_SMEM>>>(x, bcomp);
    kd_shim<<<1, 128>>>(benc);
    k2_conv_softmax<<<512, 128, K2_SMEM>>>(benc);
    k3_gather<<<1024, 256>>>(x, out);
}

// round 11
// speedup vs baseline: 1.4722x; 1.3458x over previous
#include <cuda_runtime.h>
#include <cstdint>

typedef unsigned long long u64;

// ---------- device scratch ----------
__device__ float g_feat[4 * 64 * 64 * 64];      // NHWC feat[pix][64]
__device__ float g_wk[4 * 64 * 64 * 100];       // softmaxed kernels
__device__ u64   g_wc2[2 * 256 * 16];           // k1 weights: [hf][c][16] pairs (m,m+1)
__device__ u64   g_wp2[64 * 9 * 4 * 14];        // k2 weights: [i][t][p][14] pairs (k,k+1), padded

// ---------- f32x2 helpers ----------
__device__ __forceinline__ u64 pack2(float lo, float hi) {
    u64 r; asm("mov.b64 %0, {%1, %2};" : "=l"(r) : "f"(lo), "f"(hi)); return r;
}
__device__ __forceinline__ void unpack2(u64 v, float& lo, float& hi) {
    asm("mov.b64 {%0, %1}, %2;" : "=f"(lo), "=f"(hi) : "l"(v));
}
__device__ __forceinline__ u64 fma2(u64 a, u64 b, u64 c) {
    u64 d; asm("fma.rn.f32x2 %0, %1, %2, %3;" : "=l"(d) : "l"(a), "l"(b), "l"(c)); return d;
}

// ============================================================
// K0: pack weights (R2 EXACT)
// ============================================================
__global__ void k0_pack(const float* __restrict__ Wc, const float* __restrict__ We) {
    int e = blockIdx.x * 256 + threadIdx.x;
    if (e < 8192) {
        int j = e & 15, c = (e >> 4) & 255, hf = e >> 12;
        int m0 = hf * 32 + 2 * j;
        g_wc2[e] = pack2(Wc[(size_t)m0 * 256 + c], Wc[(size_t)(m0 + 1) * 256 + c]);
    } else if (e < 8192 + 32256) {
        int e2 = e - 8192;
        int kp = e2 % 14;
        int p  = (e2 / 14) & 3;
        int t  = (e2 / 56) % 9;
        int i  = e2 / 504;
        int o0 = p * 25 + 2 * kp;
        float lo = (2 * kp < 25)     ? We[(size_t)o0 * 576 + i * 9 + t] : 0.f;
        float hi = (2 * kp + 1 < 25) ? We[(size_t)(o0 + 1) * 576 + i * 9 + t] : 0.f;
        g_wp2[e2] = pack2(lo, hi);
    }
}

// ============================================================
// K1: feat = relu(Wc @ x + bc), NHWC output (R2 EXACT)
// ============================================================
#define K1_SMEM (4096 * 8)

__global__ __launch_bounds__(128) void k1_compress(const float* __restrict__ x,
                                                   const float* __restrict__ bc) {
    extern __shared__ u64 ws[];      // [256][16] packed pairs for this half
    int tid = threadIdx.x;
    int hf  = blockIdx.x & 1;
    int pix = (blockIdx.x >> 1) * 128 + tid;

    const u64* src = g_wc2 + hf * 4096;
    for (int e = tid; e < 4096; e += 128) ws[e] = src[e];
    __syncthreads();

    int bb = pix >> 12, hw = pix & 4095;
    const float* xp = x + ((size_t)bb << 20) + hw;

    u64 acc[16];
#pragma unroll
    for (int j = 0; j < 16; j++) acc[j] = 0ull;

    for (int c = 0; c < 256; c += 4) {
        float xv[4];
#pragma unroll
        for (int u = 0; u < 4; u++) xv[u] = __ldg(xp + (size_t)(c + u) * 4096);
#pragma unroll
        for (int u = 0; u < 4; u++) {
            u64 v2 = pack2(xv[u], xv[u]);
            const ulonglong2* wr = (const ulonglong2*)(ws + (size_t)(c + u) * 16);
#pragma unroll
            for (int q = 0; q < 8; q++) {
                ulonglong2 ww = wr[q];
                acc[2 * q + 0] = fma2(v2, ww.x, acc[2 * q + 0]);
                acc[2 * q + 1] = fma2(v2, ww.y, acc[2 * q + 1]);
            }
        }
    }

    float* dst = g_feat + (size_t)pix * 64 + hf * 32;
#pragma unroll
    for (int q = 0; q < 8; q++) {
        float f0, f1, f2, f3;
        unpack2(acc[2 * q + 0], f0, f1);
        unpack2(acc[2 * q + 1], f2, f3);
        int m0 = hf * 32 + 4 * q;
        float4 v;
        v.x = fmaxf(f0 + __ldg(bc + m0 + 0), 0.f);
        v.y = fmaxf(f1 + __ldg(bc + m0 + 1), 0.f);
        v.z = fmaxf(f2 + __ldg(bc + m0 + 2), 0.f);
        v.w = fmaxf(f3 + __ldg(bc + m0 + 3), 0.f);
        ((float4*)dst)[q] = v;
    }
}

// ============================================================
// K2: 3x3 conv (64 -> 100) + bias + softmax over 25 taps (R2 EXACT)
// ============================================================
#define K2_FS_BYTES (64 * 200 * 4)               // 51200
#define K2_WQ_BYTES (4032 * 8)                   // 32256
#define K2_SMEM (K2_FS_BYTES + K2_WQ_BYTES)

__global__ __launch_bounds__(128) void k2_conv_softmax(const float* __restrict__ benc) {
    extern __shared__ char sm2[];
    float* fs = (float*)sm2;                     // [64 i][200] (3 rows x 66 cols, pad)
    u64* wq = (u64*)(sm2 + K2_FS_BYTES);         // [8 ii][9 t][4 p][14]

    int tid = threadIdx.x;
    int bb = blockIdx.x >> 6;
    int y  = blockIdx.x & 63;
    int xp = tid & 31;        // pixel pair: cols 2xp, 2xp+1
    int p  = tid >> 5;        // 0..3 (one warp per p)

    for (int pos = tid; pos < 198; pos += 128) {
        int r = pos / 66, cc = pos % 66;
        int iy = y + r - 1, ix = cc - 1;
        if (((unsigned)iy < 64u) && ((unsigned)ix < 64u)) {
            const float4* s4 = (const float4*)(g_feat + ((size_t)((bb * 64 + iy) * 64 + ix) << 6));
#pragma unroll
            for (int i0 = 0; i0 < 64; i0 += 4) {
                float4 v = s4[i0 >> 2];
                fs[(i0 + 0) * 200 + pos] = v.x;
                fs[(i0 + 1) * 200 + pos] = v.y;
                fs[(i0 + 2) * 200 + pos] = v.z;
                fs[(i0 + 3) * 200 + pos] = v.w;
            }
        } else {
#pragma unroll
            for (int i0 = 0; i0 < 64; i0++) fs[i0 * 200 + pos] = 0.f;
        }
    }

    u64 acc[28];              // [px(2)][14]
#pragma unroll
    for (int j = 0; j < 28; j++) acc[j] = 0ull;

    for (int chunk = 0; chunk < 8; chunk++) {
        __syncthreads();
        for (int e = tid; e < 4032; e += 128) wq[e] = g_wp2[chunk * 4032 + e];
        __syncthreads();

#pragma unroll 1
        for (int ii = 0; ii < 8; ii++) {
            const float* fr = fs + (chunk * 8 + ii) * 200;
            float win[3][4];
#pragma unroll
            for (int dy = 0; dy < 3; dy++) {
                const float2* rp = (const float2*)(fr + dy * 66 + 2 * xp);
                float2 a = rp[0], b = rp[1];
                win[dy][0] = a.x; win[dy][1] = a.y; win[dy][2] = b.x; win[dy][3] = b.y;
            }
#pragma unroll
            for (int t = 0; t < 9; t++) {
                int dy = t / 3, dx = t % 3;
                u64 v0 = pack2(win[dy][dx], win[dy][dx]);
                u64 v1 = pack2(win[dy][dx + 1], win[dy][dx + 1]);
                const ulonglong2* wr = (const ulonglong2*)(wq + (size_t)((ii * 9 + t) * 4 + p) * 14);
#pragma unroll
                for (int q = 0; q < 7; q++) {
                    ulonglong2 ww = wr[q];
                    acc[2 * q + 0]      = fma2(v0, ww.x, acc[2 * q + 0]);
                    acc[2 * q + 1]      = fma2(v0, ww.y, acc[2 * q + 1]);
                    acc[14 + 2 * q + 0] = fma2(v1, ww.x, acc[14 + 2 * q + 0]);
                    acc[14 + 2 * q + 1] = fma2(v1, ww.y, acc[14 + 2 * q + 1]);
                }
            }
        }
    }

#pragma unroll
    for (int px = 0; px < 2; px++) {
        float l[25];
#pragma unroll
        for (int kp = 0; kp < 13; kp++) {
            float lo, hi;
            unpack2(acc[px * 14 + kp], lo, hi);
            l[2 * kp] = lo;
            if (2 * kp + 1 < 25) l[2 * kp + 1] = hi;
        }
        float mx = -1e30f;
#pragma unroll
        for (int k = 0; k < 25; k++) {
            l[k] += __ldg(benc + p * 25 + k);
            mx = fmaxf(mx, l[k]);
        }
        float s = 0.f;
#pragma unroll
        for (int k = 0; k < 25; k++) {
            float e = __expf(l[k] - mx);
            l[k] = e;
            s += e;
        }
        float inv = 1.f / s;
        float* dst = g_wk + (size_t)((bb * 64 + y) * 64 + 2 * xp + px) * 100 + p * 25;
#pragma unroll
        for (int k = 0; k < 25; k++) dst[k] = l[k] * inv;
    }
}

// ============================================================
// K3: content-aware gather, channel-split x4 (R3 EXACT — best k3 under ncu)
// ============================================================
__device__ __forceinline__ float4 fetch4(const float* __restrict__ x, int bb, int c, int h, int e) {
    int row = e / 68, col = e % 68;
    int iy = h + row - 2, ix = col - 2;
    float4 v = make_float4(0.f, 0.f, 0.f, 0.f);
    if ((unsigned)iy < 64u && (unsigned)ix < 64u) {
        const float* b = x + (((size_t)(bb * 256 + c)) << 12) + (iy << 6) + ix;
        v.x = __ldg(b);
        v.y = __ldg(b + 4096);
        v.z = __ldg(b + 8192);
        v.w = __ldg(b + 12288);
    }
    return v;
}

__global__ __launch_bounds__(256) void k3_gather(const float* __restrict__ x,
                                                 float* __restrict__ out) {
    __shared__ float wk_s[6400];
    __shared__ float4 xs[2][340];

    int tid = threadIdx.x;
    int cg = blockIdx.x & 3;
    int h  = (blockIdx.x >> 2) & 63;
    int bb = blockIdx.x >> 8;
    int w = tid >> 2;
    int p = tid & 3;
    int cbase = cg * 64;

    {
        const float4* src = (const float4*)(g_wk + (size_t)(bb * 4096 + h * 64) * 100);
        float4* dst = (float4*)wk_s;
        for (int i = tid; i < 1600; i += 256) dst[i] = src[i];
    }

    int e1 = tid;
    int e2 = tid + 256;
    bool has2 = (e2 < 340);

    float4 pf1 = fetch4(x, bb, cbase, h, e1);
    float4 pf2 = has2 ? fetch4(x, bb, cbase, h, e2) : make_float4(0, 0, 0, 0);
    xs[0][e1] = pf1;
    if (has2) xs[0][e2] = pf2;
    __syncthreads();

    u64 wk2[25];
#pragma unroll
    for (int k = 0; k < 25; k++) {
        float v = wk_s[w * 100 + p * 25 + k];
        wk2[k] = pack2(v, v);
    }

    size_t obase = ((size_t)(bb * 256 + cbase) * 4096 + (h << 6) + w) * 4 + p;

    for (int it = 0; it < 16; it++) {
        int cur = it & 1;
        if (it < 15) {
            pf1 = fetch4(x, bb, cbase + (it + 1) * 4, h, e1);
            if (has2) pf2 = fetch4(x, bb, cbase + (it + 1) * 4, h, e2);
        }

        u64 a01 = 0ull, a23 = 0ull;
        const ulonglong2* q = (const ulonglong2*)xs[cur];
#pragma unroll
        for (int k = 0; k < 25; k++) {
            int off = (k / 5) * 68 + w + (k % 5);
            ulonglong2 v = q[off];
            a01 = fma2(v.x, wk2[k], a01);
            a23 = fma2(v.y, wk2[k], a23);
        }

        if (it < 15) {
            xs[cur ^ 1][e1] = pf1;
            if (has2) xs[cur ^ 1][e2] = pf2;
        }

        float o0, o1, o2, o3;
        unpack2(a01, o0, o1);
        unpack2(a23, o2, o3);
        size_t ob = obase + (size_t)it * 4 * 16384;
        out[ob + 0 * 16384] = o0;
        out[ob + 1 * 16384] = o1;
        out[ob + 2 * 16384] = o2;
        out[ob + 3 * 16384] = o3;

        __syncthreads();
    }
}

// ============================================================
// launch (no shim: k0, k1, k2, k3 — k3 in the profiled slot)
// ============================================================
extern "C" void kernel_launch(void* const* d_in, const int* in_sizes, int n_in,
                              void* d_out, int out_size) {
    (void)in_sizes; (void)n_in; (void)out_size;
    const float* x     = (const float*)d_in[0];
    const float* Wcomp = (const float*)d_in[1];
    const float* bcomp = (const float*)d_in[2];
    const float* Wenc  = (const float*)d_in[3];
    const float* benc  = (const float*)d_in[4];
    float* out = (float*)d_out;

    cudaFuncSetAttribute(k1_compress, cudaFuncAttributeMaxDynamicSharedMemorySize, K1_SMEM);
    cudaFuncSetAttribute(k2_conv_softmax, cudaFuncAttributeMaxDynamicSharedMemorySize, K2_SMEM);

    k0_pack<<<(8192 + 32256 + 255) / 256, 256>>>(Wcomp, Wenc);
    k1_compress<<<256, 128, K1_SMEM>>>(x, bcomp);
    k2_conv_softmax<<<256, 128, K2_SMEM>>>(benc);
    k3_gather<<<1024, 256>>>(x, out);
}

// round 12
// speedup vs baseline: 1.4887x; 1.0112x over previous
#include <cuda_runtime.h>
#include <cstdint>

typedef unsigned long long u64;

// ---------- device scratch ----------
__device__ float g_feat[4 * 64 * 64 * 64];      // NHWC feat[pix][64]
__device__ float g_wk[4 * 64 * 64 * 100];       // softmaxed kernels
__device__ u64   g_wc2[2 * 256 * 16];           // k1 weights: [hf][c][16] pairs (m,m+1)
__device__ u64   g_wp2[64 * 9 * 4 * 14];        // k2 weights: [i][t][p][14] pairs (k,k+1), padded

// ---------- f32x2 helpers ----------
__device__ __forceinline__ u64 pack2(float lo, float hi) {
    u64 r; asm("mov.b64 %0, {%1, %2};" : "=l"(r) : "f"(lo), "f"(hi)); return r;
}
__device__ __forceinline__ void unpack2(u64 v, float& lo, float& hi) {
    asm("mov.b64 {%0, %1}, %2;" : "=f"(lo), "=f"(hi) : "l"(v));
}
__device__ __forceinline__ u64 fma2(u64 a, u64 b, u64 c) {
    u64 d; asm("fma.rn.f32x2 %0, %1, %2, %3;" : "=l"(d) : "l"(a), "l"(b), "l"(c)); return d;
}

// ============================================================
// K0: pack weights (R2 EXACT)
// ============================================================
__global__ void k0_pack(const float* __restrict__ Wc, const float* __restrict__ We) {
    int e = blockIdx.x * 256 + threadIdx.x;
    if (e < 8192) {
        int j = e & 15, c = (e >> 4) & 255, hf = e >> 12;
        int m0 = hf * 32 + 2 * j;
        g_wc2[e] = pack2(Wc[(size_t)m0 * 256 + c], Wc[(size_t)(m0 + 1) * 256 + c]);
    } else if (e < 8192 + 32256) {
        int e2 = e - 8192;
        int kp = e2 % 14;
        int p  = (e2 / 14) & 3;
        int t  = (e2 / 56) % 9;
        int i  = e2 / 504;
        int o0 = p * 25 + 2 * kp;
        float lo = (2 * kp < 25)     ? We[(size_t)o0 * 576 + i * 9 + t] : 0.f;
        float hi = (2 * kp + 1 < 25) ? We[(size_t)(o0 + 1) * 576 + i * 9 + t] : 0.f;
        g_wp2[e2] = pack2(lo, hi);
    }
}

// ============================================================
// K1: feat = relu(Wc @ x + bc), NHWC output (R2 EXACT)
// ============================================================
#define K1_SMEM (4096 * 8)

__global__ __launch_bounds__(128) void k1_compress(const float* __restrict__ x,
                                                   const float* __restrict__ bc) {
    extern __shared__ u64 ws[];
    int tid = threadIdx.x;
    int hf  = blockIdx.x & 1;
    int pix = (blockIdx.x >> 1) * 128 + tid;

    const u64* src = g_wc2 + hf * 4096;
    for (int e = tid; e < 4096; e += 128) ws[e] = src[e];
    __syncthreads();

    int bb = pix >> 12, hw = pix & 4095;
    const float* xp = x + ((size_t)bb << 20) + hw;

    u64 acc[16];
#pragma unroll
    for (int j = 0; j < 16; j++) acc[j] = 0ull;

    for (int c = 0; c < 256; c += 4) {
        float xv[4];
#pragma unroll
        for (int u = 0; u < 4; u++) xv[u] = __ldg(xp + (size_t)(c + u) * 4096);
#pragma unroll
        for (int u = 0; u < 4; u++) {
            u64 v2 = pack2(xv[u], xv[u]);
            const ulonglong2* wr = (const ulonglong2*)(ws + (size_t)(c + u) * 16);
#pragma unroll
            for (int q = 0; q < 8; q++) {
                ulonglong2 ww = wr[q];
                acc[2 * q + 0] = fma2(v2, ww.x, acc[2 * q + 0]);
                acc[2 * q + 1] = fma2(v2, ww.y, acc[2 * q + 1]);
            }
        }
    }

    float* dst = g_feat + (size_t)pix * 64 + hf * 32;
#pragma unroll
    for (int q = 0; q < 8; q++) {
        float f0, f1, f2, f3;
        unpack2(acc[2 * q + 0], f0, f1);
        unpack2(acc[2 * q + 1], f2, f3);
        int m0 = hf * 32 + 4 * q;
        float4 v;
        v.x = fmaxf(f0 + __ldg(bc + m0 + 0), 0.f);
        v.y = fmaxf(f1 + __ldg(bc + m0 + 1), 0.f);
        v.z = fmaxf(f2 + __ldg(bc + m0 + 2), 0.f);
        v.w = fmaxf(f3 + __ldg(bc + m0 + 3), 0.f);
        ((float4*)dst)[q] = v;
    }
}

// ============================================================
// K2: 3x3 conv (64 -> 100) + bias + softmax — SPLIT-K over 2 warp-groups
//   grid 256 (b, row) x 256 threads; group g (128 thr) accumulates i in [32g, 32g+32)
//   per-thread inner loop, weight/feat traffic, store pattern == R2-k2 exactly;
//   warps/SM 6.9 -> 13.8. smem 83.4KB (feat 51.2 + 2x16.1 weight chunks)
// ============================================================
#define K2_FS_BYTES (64 * 200 * 4)               // 51200
#define K2_WQ_BYTES (4032 * 8)                   // 32256 = 2 groups x 2016 u64
#define K2_SMEM (K2_FS_BYTES + K2_WQ_BYTES)

__global__ __launch_bounds__(256) void k2_conv_softmax(const float* __restrict__ benc) {
    extern __shared__ char sm2[];
    float* fs = (float*)sm2;                     // [64 i][200] (3 rows x 66 cols, pad)
    u64* wq = (u64*)(sm2 + K2_FS_BYTES);         // [2 g][4 ii][9 t][4 p][14]

    int tid = threadIdx.x;
    int bb = blockIdx.x >> 6;
    int y  = blockIdx.x & 63;
    int g    = tid >> 7;      // warp-group: i in [32g, 32g+32)
    int wtid = tid & 127;
    int xp = wtid & 31;       // pixel pair: cols 2xp, 2xp+1
    int p  = wtid >> 5;       // 0..3 (one warp per p within group)

    // stage feat rows y-1..y+1, cols -1..64 (198 positions), all 64 i
    for (int pos = tid; pos < 198; pos += 256) {
        int r = pos / 66, cc = pos % 66;
        int iy = y + r - 1, ix = cc - 1;
        if (((unsigned)iy < 64u) && ((unsigned)ix < 64u)) {
            const float4* s4 = (const float4*)(g_feat + ((size_t)((bb * 64 + iy) * 64 + ix) << 6));
#pragma unroll
            for (int i0 = 0; i0 < 64; i0 += 4) {
                float4 v = s4[i0 >> 2];
                fs[(i0 + 0) * 200 + pos] = v.x;
                fs[(i0 + 1) * 200 + pos] = v.y;
                fs[(i0 + 2) * 200 + pos] = v.z;
                fs[(i0 + 3) * 200 + pos] = v.w;
            }
        } else {
#pragma unroll
            for (int i0 = 0; i0 < 64; i0++) fs[i0 * 200 + pos] = 0.f;
        }
    }

    u64 acc[28];              // [px(2)][14]
#pragma unroll
    for (int j = 0; j < 28; j++) acc[j] = 0ull;

    for (int s = 0; s < 8; s++) {
        __syncthreads();
        // stage this stage's weights: group gg gets i-range [gg*32 + s*4, +4)
        for (int e = tid; e < 4032; e += 256) {
            int gg = (e >= 2016) ? 1 : 0;
            int rest = e - gg * 2016;
            wq[e] = g_wp2[(size_t)(gg * 32 + s * 4) * 504 + rest];
        }
        __syncthreads();

        const u64* wg = wq + g * 2016;
#pragma unroll 1
        for (int ii = 0; ii < 4; ii++) {
            const float* fr = fs + (g * 32 + s * 4 + ii) * 200;
            float win[3][4];
#pragma unroll
            for (int dy = 0; dy < 3; dy++) {
                const float2* rp = (const float2*)(fr + dy * 66 + 2 * xp);
                float2 a = rp[0], b = rp[1];
                win[dy][0] = a.x; win[dy][1] = a.y; win[dy][2] = b.x; win[dy][3] = b.y;
            }
#pragma unroll
            for (int t = 0; t < 9; t++) {
                int dy = t / 3, dx = t % 3;
                u64 v0 = pack2(win[dy][dx], win[dy][dx]);
                u64 v1 = pack2(win[dy][dx + 1], win[dy][dx + 1]);
                const ulonglong2* wr = (const ulonglong2*)(wg + (size_t)((ii * 9 + t) * 4 + p) * 14);
#pragma unroll
                for (int q = 0; q < 7; q++) {
                    ulonglong2 ww = wr[q];
                    acc[2 * q + 0]      = fma2(v0, ww.x, acc[2 * q + 0]);
                    acc[2 * q + 1]      = fma2(v0, ww.y, acc[2 * q + 1]);
                    acc[14 + 2 * q + 0] = fma2(v1, ww.x, acc[14 + 2 * q + 0]);
                    acc[14 + 2 * q + 1] = fma2(v1, ww.y, acc[14 + 2 * q + 1]);
                }
            }
        }
    }

    // cross-group reduction: group 1 parks accs in smem (stride 29 to dodge conflicts)
    __syncthreads();
    u64* red = (u64*)sm2;                        // reuse feat region: 128*29*8 = 29696B
    if (g == 1) {
#pragma unroll
        for (int j = 0; j < 28; j++) red[wtid * 29 + j] = acc[j];
    }
    __syncthreads();

    if (g == 0) {
        const u64* other = red + wtid * 29;
#pragma unroll
        for (int px = 0; px < 2; px++) {
            float l[25];
#pragma unroll
            for (int kp = 0; kp < 13; kp++) {
                float lo, hi, lo2, hi2;
                unpack2(acc[px * 14 + kp], lo, hi);
                unpack2(other[px * 14 + kp], lo2, hi2);
                l[2 * kp] = lo + lo2;
                if (2 * kp + 1 < 25) l[2 * kp + 1] = hi + hi2;
            }
            float mx = -1e30f;
#pragma unroll
            for (int k = 0; k < 25; k++) {
                l[k] += __ldg(benc + p * 25 + k);
                mx = fmaxf(mx, l[k]);
            }
            float s = 0.f;
#pragma unroll
            for (int k = 0; k < 25; k++) {
                float e = __expf(l[k] - mx);
                l[k] = e;
                s += e;
            }
            float inv = 1.f / s;
            float* dst = g_wk + (size_t)((bb * 64 + y) * 64 + 2 * xp + px) * 100 + p * 25;
#pragma unroll
            for (int k = 0; k < 25; k++) dst[k] = l[k] * inv;
        }
    }
}

// ============================================================
// K3: content-aware gather, channel-split x4 (R3 EXACT)
// ============================================================
__device__ __forceinline__ float4 fetch4(const float* __restrict__ x, int bb, int c, int h, int e) {
    int row = e / 68, col = e % 68;
    int iy = h + row - 2, ix = col - 2;
    float4 v = make_float4(0.f, 0.f, 0.f, 0.f);
    if ((unsigned)iy < 64u && (unsigned)ix < 64u) {
        const float* b = x + (((size_t)(bb * 256 + c)) << 12) + (iy << 6) + ix;
        v.x = __ldg(b);
        v.y = __ldg(b + 4096);
        v.z = __ldg(b + 8192);
        v.w = __ldg(b + 12288);
    }
    return v;
}

__global__ __launch_bounds__(256) void k3_gather(const float* __restrict__ x,
                                                 float* __restrict__ out) {
    __shared__ float wk_s[6400];
    __shared__ float4 xs[2][340];

    int tid = threadIdx.x;
    int cg = blockIdx.x & 3;
    int h  = (blockIdx.x >> 2) & 63;
    int bb = blockIdx.x >> 8;
    int w = tid >> 2;
    int p = tid & 3;
    int cbase = cg * 64;

    {
        const float4* src = (const float4*)(g_wk + (size_t)(bb * 4096 + h * 64) * 100);
        float4* dst = (float4*)wk_s;
        for (int i = tid; i < 1600; i += 256) dst[i] = src[i];
    }

    int e1 = tid;
    int e2 = tid + 256;
    bool has2 = (e2 < 340);

    float4 pf1 = fetch4(x, bb, cbase, h, e1);
    float4 pf2 = has2 ? fetch4(x, bb, cbase, h, e2) : make_float4(0, 0, 0, 0);
    xs[0][e1] = pf1;
    if (has2) xs[0][e2] = pf2;
    __syncthreads();

    u64 wk2[25];
#pragma unroll
    for (int k = 0; k < 25; k++) {
        float v = wk_s[w * 100 + p * 25 + k];
        wk2[k] = pack2(v, v);
    }

    size_t obase = ((size_t)(bb * 256 + cbase) * 4096 + (h << 6) + w) * 4 + p;

    for (int it = 0; it < 16; it++) {
        int cur = it & 1;
        if (it < 15) {
            pf1 = fetch4(x, bb, cbase + (it + 1) * 4, h, e1);
            if (has2) pf2 = fetch4(x, bb, cbase + (it + 1) * 4, h, e2);
        }

        u64 a01 = 0ull, a23 = 0ull;
        const ulonglong2* q = (const ulonglong2*)xs[cur];
#pragma unroll
        for (int k = 0; k < 25; k++) {
            int off = (k / 5) * 68 + w + (k % 5);
            ulonglong2 v = q[off];
            a01 = fma2(v.x, wk2[k], a01);
            a23 = fma2(v.y, wk2[k], a23);
        }

        if (it < 15) {
            xs[cur ^ 1][e1] = pf1;
            if (has2) xs[cur ^ 1][e2] = pf2;
        }

        float o0, o1, o2, o3;
        unpack2(a01, o0, o1);
        unpack2(a23, o2, o3);
        size_t ob = obase + (size_t)it * 4 * 16384;
        out[ob + 0 * 16384] = o0;
        out[ob + 1 * 16384] = o1;
        out[ob + 2 * 16384] = o2;
        out[ob + 3 * 16384] = o3;

        __syncthreads();
    }
}

// ============================================================
// launch: k0, k1, k2, k3 (k3 in the profiled 4th slot)
// ============================================================
extern "C" void kernel_launch(void* const* d_in, const int* in_sizes, int n_in,
                              void* d_out, int out_size) {
    (void)in_sizes; (void)n_in; (void)out_size;
    const float* x     = (const float*)d_in[0];
    const float* Wcomp = (const float*)d_in[1];
    const float* bcomp = (const float*)d_in[2];
    const float* Wenc  = (const float*)d_in[3];
    const float* benc  = (const float*)d_in[4];
    float* out = (float*)d_out;

    cudaFuncSetAttribute(k1_compress, cudaFuncAttributeMaxDynamicSharedMemorySize, K1_SMEM);
    cudaFuncSetAttribute(k2_conv_softmax, cudaFuncAttributeMaxDynamicSharedMemorySize, K2_SMEM);

    k0_pack<<<(8192 + 32256 + 255) / 256, 256>>>(Wcomp, Wenc);
    k1_compress<<<256, 128, K1_SMEM>>>(x, bcomp);
    k2_conv_softmax<<<256, 256, K2_SMEM>>>(benc);
    k3_gather<<<1024, 256>>>(x, out);
}